// round 6
// baseline (speedup 1.0000x reference)
#include <cuda_runtime.h>
#include <cstdint>

#define BM 128
#define BN 128
#define BK 32
#define NT 256

static __device__ __forceinline__ uint32_t s2u(const void* p) {
    uint32_t a;
    asm("{ .reg .u64 t; cvta.to.shared.u64 t, %1; cvt.u32.u64 %0, t; }" : "=r"(a) : "l"(p));
    return a;
}
static __device__ __forceinline__ uint32_t f2tf32(float x) {
    uint32_t r; asm("cvt.rna.tf32.f32 %0, %1;" : "=r"(r) : "f"(x)); return r;
}
static __device__ __forceinline__ void ldsm4(uint32_t& r0, uint32_t& r1,
                                             uint32_t& r2, uint32_t& r3, uint32_t addr) {
    asm volatile("ldmatrix.sync.aligned.m8n8.x4.shared.b16 {%0,%1,%2,%3}, [%4];"
                 : "=r"(r0), "=r"(r1), "=r"(r2), "=r"(r3) : "r"(addr));
}
static __device__ __forceinline__ void mma_tf32(float c[4],
                                                uint32_t a0, uint32_t a1, uint32_t a2, uint32_t a3,
                                                uint32_t b0, uint32_t b1) {
    asm volatile(
        "mma.sync.aligned.m16n8k8.row.col.f32.tf32.tf32.f32 "
        "{%0,%1,%2,%3}, {%4,%5,%6,%7}, {%8,%9}, {%0,%1,%2,%3};\n"
        : "+f"(c[0]), "+f"(c[1]), "+f"(c[2]), "+f"(c[3])
        : "r"(a0), "r"(a1), "r"(a2), "r"(a3), "r"(b0), "r"(b1));
}

__global__ void __launch_bounds__(NT, 2)
bsl_ldsm2(const float* __restrict__ X, const float* __restrict__ W,
          const float* __restrict__ Bias, float* __restrict__ Y) {
    const int K = 4096, N = 4096;
    extern __shared__ uint32_t sm[];
    const uint32_t sbase  = s2u(sm);
    const uint32_t AsByte = sbase;                       // [2][BM*BK] words
    const uint32_t BsByte = sbase + 2u * BM * BK * 4u;   // [2][BN*BK] words

    const int tid  = threadIdx.x;
    const int lane = tid & 31;
    const int warp = tid >> 5;
    const int wm   = warp >> 2;          // 0..1 (M, 64 rows each)
    const int wn   = warp & 3;           // 0..3 (N, 32 cols each)

    const int bm = blockIdx.y * BM;
    const int bn = blockIdx.x * BN;

    // ---- producer mapping: 8 threads per 128B row, 4 rows each (stride 32)
    const int arow = tid >> 3;           // 0..31
    const int kq   = tid & 7;            // 16B quad within row
    const float* Ag = X + (size_t)(bm + arow) * K + kq * 4;
    const float* Wg = W + (size_t)(bn + arow) * K + kq * 4;
    const int swq = (kq * 4) ^ ((arow & 7) * 4);  // row stride 32 preserves row&7
    int sA[4], sB[4];
    #pragma unroll
    for (int i = 0; i < 4; ++i) {
        sA[i] = (arow + i * 32) * BK + swq;
        sB[i] = (arow + i * 32) * BK + swq;
    }

    // ---- ldmatrix per-thread addressing (hoisted, pure adds in the loop)
    const int g = lane >> 3, r = lane & 7;
    const int ga = g >> 1, gb = g & 1;
    uint32_t aoff[4], boff[2];
    #pragma unroll
    for (int mt = 0; mt < 4; ++mt)
        aoff[mt] = (uint32_t)((wm * 64 + mt * 16 + (g & 1) * 8 + r) * 128);
    #pragma unroll
    for (int ntp = 0; ntp < 2; ++ntp)
        boff[ntp] = (uint32_t)((wn * 32 + (2 * ntp + (g >> 1)) * 8 + r) * 128);
    uint32_t qxa[4], qxb[4];
    #pragma unroll
    for (int kk = 0; kk < 4; ++kk) {
        qxa[kk] = (uint32_t)(((2 * kk + ga) ^ r) * 16);
        qxb[kk] = (uint32_t)(((2 * kk + gb) ^ r) * 16);
    }

    float acc[4][4][4];
    #pragma unroll
    for (int mt = 0; mt < 4; ++mt)
        #pragma unroll
        for (int nt = 0; nt < 4; ++nt)
            #pragma unroll
            for (int j = 0; j < 4; ++j) acc[mt][nt][j] = 0.0f;

    float4 ra[4], rb[4];
    const int nk = K / BK;               // 128

    // prologue: stage 0
    #pragma unroll
    for (int i = 0; i < 4; ++i) {
        ra[i] = *(const float4*)(Ag + (size_t)(i * 32) * K);
        rb[i] = *(const float4*)(Wg + (size_t)(i * 32) * K);
    }
    #pragma unroll
    for (int i = 0; i < 4; ++i) {
        uint4 ua = { f2tf32(ra[i].x), f2tf32(ra[i].y), f2tf32(ra[i].z), f2tf32(ra[i].w) };
        *(uint4*)(sm + sA[i]) = ua;
        uint4 ub = { f2tf32(rb[i].x), f2tf32(rb[i].y), f2tf32(rb[i].z), f2tf32(rb[i].w) };
        *(uint4*)(sm + 2 * BM * BK + sB[i]) = ub;
    }
    __syncthreads();

    int cur = 0;
    for (int t = 0; t < nk; ++t) {
        if (t + 1 < nk) {
            const float* Ap = Ag + (size_t)(t + 1) * BK;
            const float* Wp = Wg + (size_t)(t + 1) * BK;
            #pragma unroll
            for (int i = 0; i < 4; ++i) {
                ra[i] = *(const float4*)(Ap + (size_t)(i * 32) * K);
                rb[i] = *(const float4*)(Wp + (size_t)(i * 32) * K);
            }
        }

        const uint32_t Ab = AsByte + (uint32_t)cur * (BM * BK * 4);
        const uint32_t Bb = BsByte + (uint32_t)cur * (BN * BK * 4);
        #pragma unroll
        for (int kk = 0; kk < 4; ++kk) {
            uint32_t a[4][4], b[4][2];
            #pragma unroll
            for (int mt = 0; mt < 4; ++mt)
                ldsm4(a[mt][0], a[mt][1], a[mt][2], a[mt][3], Ab + aoff[mt] + qxa[kk]);
            #pragma unroll
            for (int ntp = 0; ntp < 2; ++ntp)
                ldsm4(b[2 * ntp][0], b[2 * ntp][1], b[2 * ntp + 1][0], b[2 * ntp + 1][1],
                      Bb + boff[ntp] + qxb[kk]);
            #pragma unroll
            for (int mt = 0; mt < 4; ++mt)
                #pragma unroll
                for (int nt = 0; nt < 4; ++nt)
                    mma_tf32(acc[mt][nt],
                             a[mt][0], a[mt][1], a[mt][2], a[mt][3],
                             b[nt][0], b[nt][1]);
        }

        if (t + 1 < nk) {
            uint32_t* Asn = sm + (cur ^ 1) * (BM * BK);
            uint32_t* Bsn = sm + 2 * BM * BK + (cur ^ 1) * (BN * BK);
            #pragma unroll
            for (int i = 0; i < 4; ++i) {
                uint4 ua = { f2tf32(ra[i].x), f2tf32(ra[i].y), f2tf32(ra[i].z), f2tf32(ra[i].w) };
                *(uint4*)(Asn + sA[i]) = ua;
                uint4 ub = { f2tf32(rb[i].x), f2tf32(rb[i].y), f2tf32(rb[i].z), f2tf32(rb[i].w) };
                *(uint4*)(Bsn + sB[i]) = ub;
            }
        }
        __syncthreads();
        cur ^= 1;
    }

    // ---- epilogue: bias + fp32 store
    const int row = lane >> 2;
    const int col = lane & 3;
    #pragma unroll
    for (int nt = 0; nt < 4; ++nt) {
        const int gn = bn + wn * 32 + nt * 8 + col * 2;
        const float2 bb = *(const float2*)(Bias + gn);
        #pragma unroll
        for (int mt = 0; mt < 4; ++mt) {
            const int gm = bm + wm * 64 + mt * 16 + row;
            float2 v0, v1;
            v0.x = acc[mt][nt][0] + bb.x; v0.y = acc[mt][nt][1] + bb.y;
            v1.x = acc[mt][nt][2] + bb.x; v1.y = acc[mt][nt][3] + bb.y;
            *(float2*)(Y + (size_t)gm * N + gn)       = v0;
            *(float2*)(Y + (size_t)(gm + 8) * N + gn) = v1;
        }
    }
}

extern "C" void kernel_launch(void* const* d_in, const int* in_sizes, int n_in,
                              void* d_out, int out_size) {
    const float* X    = (const float*)d_in[0];   // [M, 4096]
    const float* W    = (const float*)d_in[1];   // [4096, 4096]
    const float* Bias = (const float*)d_in[2];   // [4096]
    float* Y = (float*)d_out;

    const int K = 4096;
    const int M = in_sizes[0] / K;               // 8192

    const size_t smem_bytes = (size_t)(2 * BM * BK + 2 * BN * BK) * 4; // 65536
    cudaFuncSetAttribute(bsl_ldsm2, cudaFuncAttributeMaxDynamicSharedMemorySize,
                         (int)smem_bytes);

    dim3 grid(4096 / BN, M / BM);   // (32, 64), N fast for L2 reuse
    bsl_ldsm2<<<grid, NT, smem_bytes>>>(X, W, Bias, Y);
}

// round 7
// speedup vs baseline: 1.1022x; 1.1022x over previous
#include <cuda_runtime.h>
#include <cstdint>

#define BM 128
#define BN 256
#define BK 32
#define NT 256

static __device__ __forceinline__ uint32_t s2u(const void* p) {
    uint32_t a;
    asm("{ .reg .u64 t; cvta.to.shared.u64 t, %1; cvt.u32.u64 %0, t; }" : "=r"(a) : "l"(p));
    return a;
}
static __device__ __forceinline__ uint32_t f2tf32(float x) {
    uint32_t r; asm("cvt.rna.tf32.f32 %0, %1;" : "=r"(r) : "f"(x)); return r;
}
static __device__ __forceinline__ void ldsm4(uint32_t& r0, uint32_t& r1,
                                             uint32_t& r2, uint32_t& r3, uint32_t addr) {
    asm volatile("ldmatrix.sync.aligned.m8n8.x4.shared.b16 {%0,%1,%2,%3}, [%4];"
                 : "=r"(r0), "=r"(r1), "=r"(r2), "=r"(r3) : "r"(addr));
}
static __device__ __forceinline__ void mma_tf32(float c[4],
                                                uint32_t a0, uint32_t a1, uint32_t a2, uint32_t a3,
                                                uint32_t b0, uint32_t b1) {
    asm volatile(
        "mma.sync.aligned.m16n8k8.row.col.f32.tf32.tf32.f32 "
        "{%0,%1,%2,%3}, {%4,%5,%6,%7}, {%8,%9}, {%0,%1,%2,%3};\n"
        : "+f"(c[0]), "+f"(c[1]), "+f"(c[2]), "+f"(c[3])
        : "r"(a0), "r"(a1), "r"(a2), "r"(a3), "r"(b0), "r"(b1));
}

__global__ void __launch_bounds__(NT, 1)
bsl_w64(const float* __restrict__ X, const float* __restrict__ W,
        const float* __restrict__ Bias, float* __restrict__ Y) {
    const int K = 4096, N = 4096;
    extern __shared__ uint32_t sm[];
    const uint32_t sbase  = s2u(sm);
    const uint32_t AsByte = sbase;                       // [2][BM*BK] words
    const uint32_t BsByte = sbase + 2u * BM * BK * 4u;   // [2][BN*BK] words

    const int tid  = threadIdx.x;
    const int lane = tid & 31;
    const int warp = tid >> 5;
    const int wm   = warp >> 2;          // 0..1 (M, 64 rows each)
    const int wn   = warp & 3;           // 0..3 (N, 64 cols each)

    const int bm = blockIdx.y * BM;
    const int bn = blockIdx.x * BN;

    // ---- producer mapping: 8 threads per 128B row (32 rows per pass)
    const int arow = tid >> 3;           // 0..31
    const int kq   = tid & 7;            // 16B quad within row
    const float* Ag = X + (size_t)(bm + arow) * K + kq * 4;
    const float* Wg = W + (size_t)(bn + arow) * K + kq * 4;
    const int swq = (kq * 4) ^ ((arow & 7) * 4);  // row stride 32 preserves row&7
    int sA[4], sB[8];
    #pragma unroll
    for (int i = 0; i < 4; ++i) sA[i] = (arow + i * 32) * BK + swq;
    #pragma unroll
    for (int j = 0; j < 8; ++j) sB[j] = (arow + j * 32) * BK + swq;

    // ---- ldmatrix per-thread addressing (hoisted)
    const int g = lane >> 3, r = lane & 7;
    const int ga = g >> 1, gb = g & 1;
    uint32_t aoff[4], boff[4];
    #pragma unroll
    for (int mt = 0; mt < 4; ++mt)
        aoff[mt] = (uint32_t)((wm * 64 + mt * 16 + (g & 1) * 8 + r) * 128);
    #pragma unroll
    for (int ntp = 0; ntp < 4; ++ntp)
        boff[ntp] = (uint32_t)((wn * 64 + (2 * ntp + (g >> 1)) * 8 + r) * 128);
    uint32_t qxa[4], qxb[4];
    #pragma unroll
    for (int kk = 0; kk < 4; ++kk) {
        qxa[kk] = (uint32_t)(((2 * kk + ga) ^ r) * 16);
        qxb[kk] = (uint32_t)(((2 * kk + gb) ^ r) * 16);
    }

    float acc[4][8][4];
    #pragma unroll
    for (int mt = 0; mt < 4; ++mt)
        #pragma unroll
        for (int nt = 0; nt < 8; ++nt)
            #pragma unroll
            for (int j = 0; j < 4; ++j) acc[mt][nt][j] = 0.0f;

    float4 ra[4], rb[8];
    const int nk = K / BK;               // 128

    // prologue: stage 0
    #pragma unroll
    for (int i = 0; i < 4; ++i) ra[i] = *(const float4*)(Ag + (size_t)(i * 32) * K);
    #pragma unroll
    for (int j = 0; j < 8; ++j) rb[j] = *(const float4*)(Wg + (size_t)(j * 32) * K);
    #pragma unroll
    for (int i = 0; i < 4; ++i) {
        uint4 u = { f2tf32(ra[i].x), f2tf32(ra[i].y), f2tf32(ra[i].z), f2tf32(ra[i].w) };
        *(uint4*)(sm + sA[i]) = u;
    }
    #pragma unroll
    for (int j = 0; j < 8; ++j) {
        uint4 u = { f2tf32(rb[j].x), f2tf32(rb[j].y), f2tf32(rb[j].z), f2tf32(rb[j].w) };
        *(uint4*)(sm + 2 * BM * BK + sB[j]) = u;
    }
    __syncthreads();

    int cur = 0;
    for (int t = 0; t < nk; ++t) {
        if (t + 1 < nk) {
            const float* Ap = Ag + (size_t)(t + 1) * BK;
            const float* Wp = Wg + (size_t)(t + 1) * BK;
            #pragma unroll
            for (int i = 0; i < 4; ++i) ra[i] = *(const float4*)(Ap + (size_t)(i * 32) * K);
            #pragma unroll
            for (int j = 0; j < 8; ++j) rb[j] = *(const float4*)(Wp + (size_t)(j * 32) * K);
        }

        const uint32_t Ab = AsByte + (uint32_t)cur * (BM * BK * 4);
        const uint32_t Bb = BsByte + (uint32_t)cur * (BN * BK * 4);
        #pragma unroll
        for (int kk = 0; kk < 4; ++kk) {
            uint32_t a[4][4], b[8][2];
            #pragma unroll
            for (int mt = 0; mt < 4; ++mt)
                ldsm4(a[mt][0], a[mt][1], a[mt][2], a[mt][3], Ab + aoff[mt] + qxa[kk]);
            #pragma unroll
            for (int ntp = 0; ntp < 4; ++ntp)
                ldsm4(b[2 * ntp][0], b[2 * ntp][1], b[2 * ntp + 1][0], b[2 * ntp + 1][1],
                      Bb + boff[ntp] + qxb[kk]);
            #pragma unroll
            for (int mt = 0; mt < 4; ++mt)
                #pragma unroll
                for (int nt = 0; nt < 8; ++nt)
                    mma_tf32(acc[mt][nt],
                             a[mt][0], a[mt][1], a[mt][2], a[mt][3],
                             b[nt][0], b[nt][1]);
        }

        if (t + 1 < nk) {
            uint32_t* Asn = sm + (cur ^ 1) * (BM * BK);
            uint32_t* Bsn = sm + 2 * BM * BK + (cur ^ 1) * (BN * BK);
            #pragma unroll
            for (int i = 0; i < 4; ++i) {
                uint4 u = { f2tf32(ra[i].x), f2tf32(ra[i].y), f2tf32(ra[i].z), f2tf32(ra[i].w) };
                *(uint4*)(Asn + sA[i]) = u;
            }
            #pragma unroll
            for (int j = 0; j < 8; ++j) {
                uint4 u = { f2tf32(rb[j].x), f2tf32(rb[j].y), f2tf32(rb[j].z), f2tf32(rb[j].w) };
                *(uint4*)(Bsn + sB[j]) = u;
            }
        }
        __syncthreads();
        cur ^= 1;
    }

    // ---- epilogue: bias + fp32 store
    const int row = lane >> 2;
    const int col = lane & 3;
    #pragma unroll
    for (int nt = 0; nt < 8; ++nt) {
        const int gn = bn + wn * 64 + nt * 8 + col * 2;
        const float2 bb = *(const float2*)(Bias + gn);
        #pragma unroll
        for (int mt = 0; mt < 4; ++mt) {
            const int gm = bm + wm * 64 + mt * 16 + row;
            float2 v0, v1;
            v0.x = acc[mt][nt][0] + bb.x; v0.y = acc[mt][nt][1] + bb.y;
            v1.x = acc[mt][nt][2] + bb.x; v1.y = acc[mt][nt][3] + bb.y;
            *(float2*)(Y + (size_t)gm * N + gn)       = v0;
            *(float2*)(Y + (size_t)(gm + 8) * N + gn) = v1;
        }
    }
}

extern "C" void kernel_launch(void* const* d_in, const int* in_sizes, int n_in,
                              void* d_out, int out_size) {
    const float* X    = (const float*)d_in[0];   // [M, 4096]
    const float* W    = (const float*)d_in[1];   // [4096, 4096]
    const float* Bias = (const float*)d_in[2];   // [4096]
    float* Y = (float*)d_out;

    const int K = 4096;
    const int M = in_sizes[0] / K;               // 8192

    const size_t smem_bytes = (size_t)(2 * BM * BK + 2 * BN * BK) * 4; // 98304
    cudaFuncSetAttribute(bsl_w64, cudaFuncAttributeMaxDynamicSharedMemorySize,
                         (int)smem_bytes);

    dim3 grid(4096 / BN, M / BM);   // (16, 64), N fast for L2 reuse
    bsl_w64<<<grid, NT, smem_bytes>>>(X, W, Bias, Y);
}

// round 9
// speedup vs baseline: 1.1272x; 1.0227x over previous
#include <cuda_runtime.h>
#include <cstdint>

#define BM 128
#define BN 256
#define BK 32
#define NT 256
#define NSTG 4

// tf32-rounded copies of the inputs (scratch via __device__ globals; no allocs)
__device__ float g_Xc[8192u * 4096u];
__device__ float g_Wc[4096u * 4096u];

static __device__ __forceinline__ uint32_t s2u(const void* p) {
    uint32_t a;
    asm("{ .reg .u64 t; cvta.to.shared.u64 t, %1; cvt.u32.u64 %0, t; }" : "=r"(a) : "l"(p));
    return a;
}
static __device__ __forceinline__ uint32_t f2tf32(float x) {
    uint32_t r; asm("cvt.rna.tf32.f32 %0, %1;" : "=r"(r) : "f"(x)); return r;
}
static __device__ __forceinline__ void cpasync16(uint32_t dst, const void* src) {
    asm volatile("cp.async.cg.shared.global [%0], [%1], 16;" :: "r"(dst), "l"(src));
}
static __device__ __forceinline__ void cpcommit() {
    asm volatile("cp.async.commit_group;" ::: "memory");
}
template <int N_> static __device__ __forceinline__ void cpwait() {
    asm volatile("cp.async.wait_group %0;" :: "n"(N_) : "memory");
}
static __device__ __forceinline__ void ldsm4(uint32_t& r0, uint32_t& r1,
                                             uint32_t& r2, uint32_t& r3, uint32_t addr) {
    asm volatile("ldmatrix.sync.aligned.m8n8.x4.shared.b16 {%0,%1,%2,%3}, [%4];"
                 : "=r"(r0), "=r"(r1), "=r"(r2), "=r"(r3) : "r"(addr));
}
static __device__ __forceinline__ void mma_tf32(float c[4],
                                                uint32_t a0, uint32_t a1, uint32_t a2, uint32_t a3,
                                                uint32_t b0, uint32_t b1) {
    asm volatile(
        "mma.sync.aligned.m16n8k8.row.col.f32.tf32.tf32.f32 "
        "{%0,%1,%2,%3}, {%4,%5,%6,%7}, {%8,%9}, {%0,%1,%2,%3};\n"
        : "+f"(c[0]), "+f"(c[1]), "+f"(c[2]), "+f"(c[3])
        : "r"(a0), "r"(a1), "r"(a2), "r"(a3), "r"(b0), "r"(b1));
}

__global__ void __launch_bounds__(256) cvt_tf32(const float4* __restrict__ src,
                                                float4* __restrict__ dst, int n4) {
    int i = blockIdx.x * 256 + threadIdx.x;
    int stride = gridDim.x * 256;
    for (; i < n4; i += stride) {
        float4 v = src[i];
        float4 o;
        o.x = __uint_as_float(f2tf32(v.x));
        o.y = __uint_as_float(f2tf32(v.y));
        o.z = __uint_as_float(f2tf32(v.z));
        o.w = __uint_as_float(f2tf32(v.w));
        dst[i] = o;
    }
}

__global__ void __launch_bounds__(NT, 1)
bsl_cpa(const float* __restrict__ Bias, float* __restrict__ Y) {
    const int K = 4096, N = 4096;
    extern __shared__ uint32_t sm[];
    const uint32_t sbase = s2u(sm);
    const uint32_t ABYTES = BM * BK * 4;      // 16 KB per A stage
    const uint32_t BBYTES = BN * BK * 4;      // 32 KB per B stage
    const uint32_t OFFB   = NSTG * ABYTES;

    const int tid  = threadIdx.x;
    const int lane = tid & 31;
    const int warp = tid >> 5;
    const int wm   = warp >> 2;          // 0..1 (M, 64 rows)
    const int wn   = warp & 3;           // 0..3 (N, 64 cols)

    const int bm = blockIdx.y * BM;
    const int bn = blockIdx.x * BN;

    // ---- producer mapping: 8 threads per 128B row
    const int arow = tid >> 3;           // 0..31
    const int kq   = tid & 7;            // 16B quad within row
    const float* Ag = g_Xc + (size_t)(bm + arow) * K + kq * 4;
    const float* Wg = g_Wc + (size_t)(bn + arow) * K + kq * 4;
    const int swb = ((kq * 4) ^ ((arow & 7) * 4)) * 4;  // byte offset within row
    uint32_t sA[4], sB[8];
    #pragma unroll
    for (int i = 0; i < 4; ++i) sA[i] = (uint32_t)((arow + i * 32) * 128 + swb);
    #pragma unroll
    for (int j = 0; j < 8; ++j) sB[j] = (uint32_t)((arow + j * 32) * 128 + swb);

    // ---- ldmatrix addressing (hoisted)
    const int g = lane >> 3, r = lane & 7;
    const int ga = g >> 1, gb = g & 1;
    uint32_t aoff[4], boff[4];
    #pragma unroll
    for (int mt = 0; mt < 4; ++mt)
        aoff[mt] = (uint32_t)((wm * 64 + mt * 16 + (g & 1) * 8 + r) * 128);
    #pragma unroll
    for (int ntp = 0; ntp < 4; ++ntp)
        boff[ntp] = (uint32_t)((wn * 64 + (2 * ntp + (g >> 1)) * 8 + r) * 128);
    uint32_t qxa[4], qxb[4];
    #pragma unroll
    for (int kk = 0; kk < 4; ++kk) {
        qxa[kk] = (uint32_t)(((2 * kk + ga) ^ r) * 16);
        qxb[kk] = (uint32_t)(((2 * kk + gb) ^ r) * 16);
    }

    float acc[4][8][4];
    #pragma unroll
    for (int mt = 0; mt < 4; ++mt)
        #pragma unroll
        for (int nt = 0; nt < 8; ++nt)
            #pragma unroll
            for (int j = 0; j < 4; ++j) acc[mt][nt][j] = 0.0f;

    const int nk = K / BK;               // 128

    // stage issue: 4 A + 8 B cp.asyncs per thread
    auto issue = [&](int t, int s) {
        const uint32_t Ab = sbase + (uint32_t)s * ABYTES;
        const uint32_t Bb = sbase + OFFB + (uint32_t)s * BBYTES;
        const float* Ap = Ag + (size_t)t * BK;
        const float* Wp = Wg + (size_t)t * BK;
        #pragma unroll
        for (int i = 0; i < 4; ++i) cpasync16(Ab + sA[i], Ap + (size_t)(i * 32) * K);
        #pragma unroll
        for (int j = 0; j < 8; ++j) cpasync16(Bb + sB[j], Wp + (size_t)(j * 32) * K);
    };

    // prologue: stages 0..2
    #pragma unroll
    for (int s = 0; s < NSTG - 1; ++s) { issue(s, s); cpcommit(); }

    for (int t = 0; t < nk; ++t) {
        cpwait<NSTG - 2>();
        __syncthreads();

        if (t + NSTG - 1 < nk) issue(t + NSTG - 1, (t + NSTG - 1) & (NSTG - 1));
        cpcommit();

        const uint32_t Ab = sbase + (uint32_t)(t & (NSTG - 1)) * ABYTES;
        const uint32_t Bb = sbase + OFFB + (uint32_t)(t & (NSTG - 1)) * BBYTES;
        #pragma unroll
        for (int kk = 0; kk < 4; ++kk) {
            uint32_t a[4][4], b[8][2];
            #pragma unroll
            for (int mt = 0; mt < 4; ++mt)
                ldsm4(a[mt][0], a[mt][1], a[mt][2], a[mt][3], Ab + aoff[mt] + qxa[kk]);
            #pragma unroll
            for (int ntp = 0; ntp < 4; ++ntp)
                ldsm4(b[2 * ntp][0], b[2 * ntp][1], b[2 * ntp + 1][0], b[2 * ntp + 1][1],
                      Bb + boff[ntp] + qxb[kk]);
            #pragma unroll
            for (int mt = 0; mt < 4; ++mt)
                #pragma unroll
                for (int nt = 0; nt < 8; ++nt)
                    mma_tf32(acc[mt][nt],
                             a[mt][0], a[mt][1], a[mt][2], a[mt][3],
                             b[nt][0], b[nt][1]);
        }
    }

    // ---- epilogue: bias + fp32 store
    const int row = lane >> 2;
    const int col = lane & 3;
    #pragma unroll
    for (int nt = 0; nt < 8; ++nt) {
        const int gn = bn + wn * 64 + nt * 8 + col * 2;
        const float2 bb = *(const float2*)(Bias + gn);
        #pragma unroll
        for (int mt = 0; mt < 4; ++mt) {
            const int gm = bm + wm * 64 + mt * 16 + row;
            float2 v0, v1;
            v0.x = acc[mt][nt][0] + bb.x; v0.y = acc[mt][nt][1] + bb.y;
            v1.x = acc[mt][nt][2] + bb.x; v1.y = acc[mt][nt][3] + bb.y;
            *(float2*)(Y + (size_t)gm * N + gn)       = v0;
            *(float2*)(Y + (size_t)(gm + 8) * N + gn) = v1;
        }
    }
}

extern "C" void kernel_launch(void* const* d_in, const int* in_sizes, int n_in,
                              void* d_out, int out_size) {
    const float* X    = (const float*)d_in[0];   // [M, 4096]
    const float* W    = (const float*)d_in[1];   // [4096, 4096]
    const float* Bias = (const float*)d_in[2];   // [4096]
    float* Y = (float*)d_out;

    const int K = 4096;
    const int M = in_sizes[0] / K;               // 8192

    float *Xc, *Wc;
    cudaGetSymbolAddress((void**)&Xc, g_Xc);
    cudaGetSymbolAddress((void**)&Wc, g_Wc);

    // pre-round inputs to tf32 (bit-identical operands vs in-loop cvt.rna)
    const int n4x = (M * K) / 4, n4w = (4096 * K) / 4;
    cvt_tf32<<<4096, 256>>>((const float4*)X, (float4*)Xc, n4x);
    cvt_tf32<<<4096, 256>>>((const float4*)W, (float4*)Wc, n4w);

    const size_t smem_bytes = (size_t)NSTG * (BM * BK + BN * BK) * 4; // 196608
    cudaFuncSetAttribute(bsl_cpa, cudaFuncAttributeMaxDynamicSharedMemorySize,
                         (int)smem_bytes);

    dim3 grid(4096 / BN, M / BM);   // (16, 64), N fast for L2 reuse
    bsl_cpa<<<grid, NT, smem_bytes>>>(Bias, Y);
}

// round 13
// speedup vs baseline: 1.1898x; 1.0555x over previous
#include <cuda_runtime.h>
#include <cstdint>

#define BM 128
#define BN 256
#define BK 32
#define NT 256
#define NSTG 4

// tf32-rounded copies of the inputs + block-nonzero mask (scratch; no allocs)
__device__ float g_Xc[8192u * 4096u];
__device__ float g_Wc[4096u * 4096u];
__device__ uint32_t g_maskW[256 * 8];   // bit kb of word [nb*8 + kb/32]: block nonzero

static __device__ __forceinline__ uint32_t s2u(const void* p) {
    uint32_t a;
    asm("{ .reg .u64 t; cvta.to.shared.u64 t, %1; cvt.u32.u64 %0, t; }" : "=r"(a) : "l"(p));
    return a;
}
static __device__ __forceinline__ uint32_t f2tf32(float x) {
    uint32_t r; asm("cvt.rna.tf32.f32 %0, %1;" : "=r"(r) : "f"(x)); return r;
}
static __device__ __forceinline__ void cpasync16(uint32_t dst, const void* src) {
    asm volatile("cp.async.cg.shared.global [%0], [%1], 16;" :: "r"(dst), "l"(src));
}
static __device__ __forceinline__ void cpcommit() {
    asm volatile("cp.async.commit_group;" ::: "memory");
}
template <int N_> static __device__ __forceinline__ void cpwait() {
    asm volatile("cp.async.wait_group %0;" :: "n"(N_) : "memory");
}
static __device__ __forceinline__ void ldsm4(uint32_t& r0, uint32_t& r1,
                                             uint32_t& r2, uint32_t& r3, uint32_t addr) {
    asm volatile("ldmatrix.sync.aligned.m8n8.x4.shared.b16 {%0,%1,%2,%3}, [%4];"
                 : "=r"(r0), "=r"(r1), "=r"(r2), "=r"(r3) : "r"(addr));
}
static __device__ __forceinline__ void mma_tf32(float c[4],
                                                uint32_t a0, uint32_t a1, uint32_t a2, uint32_t a3,
                                                uint32_t b0, uint32_t b1) {
    asm volatile(
        "mma.sync.aligned.m16n8k8.row.col.f32.tf32.tf32.f32 "
        "{%0,%1,%2,%3}, {%4,%5,%6,%7}, {%8,%9}, {%0,%1,%2,%3};\n"
        : "+f"(c[0]), "+f"(c[1]), "+f"(c[2]), "+f"(c[3])
        : "r"(a0), "r"(a1), "r"(a2), "r"(a3), "r"(b0), "r"(b1));
}

__global__ void __launch_bounds__(256) cvt_tf32(const float4* __restrict__ src,
                                                float4* __restrict__ dst, int n4) {
    int i = blockIdx.x * 256 + threadIdx.x;
    int stride = gridDim.x * 256;
    for (; i < n4; i += stride) {
        float4 v = src[i];
        float4 o;
        o.x = __uint_as_float(f2tf32(v.x));
        o.y = __uint_as_float(f2tf32(v.y));
        o.z = __uint_as_float(f2tf32(v.z));
        o.w = __uint_as_float(f2tf32(v.w));
        dst[i] = o;
    }
}

// one warp per 16x16 block: bit set iff any element nonzero (atomicOr idempotent)
__global__ void __launch_bounds__(256) mask_kernel(const float* __restrict__ W) {
    const int gid  = blockIdx.x * 8 + (threadIdx.x >> 5);   // block id 0..65535
    const int lane = threadIdx.x & 31;
    const int nb = gid >> 8, kb = gid & 255;
    const int i  = lane >> 1;
    const int j8 = (lane & 1) * 8;
    const float4* p = (const float4*)(W + (size_t)(nb * 16 + i) * 4096 + kb * 16 + j8);
    float4 a = p[0], b = p[1];
    bool nz = (a.x != 0.f) | (a.y != 0.f) | (a.z != 0.f) | (a.w != 0.f)
            | (b.x != 0.f) | (b.y != 0.f) | (b.z != 0.f) | (b.w != 0.f);
    unsigned bal = __ballot_sync(0xFFFFFFFFu, nz);
    if (lane == 0 && bal)
        atomicOr(&g_maskW[nb * 8 + (kb >> 5)], 1u << (kb & 31));
}

__global__ void __launch_bounds__(NT, 1)
bsl_sp(const float* __restrict__ Bias, float* __restrict__ Y) {
    const int K = 4096, N = 4096;
    extern __shared__ uint32_t sm[];
    const uint32_t sbase = s2u(sm);
    const uint32_t ABYTES = BM * BK * 4;      // 16 KB per A stage
    const uint32_t BBYTES = BN * BK * 4;      // 32 KB per B stage
    const uint32_t OFFB   = NSTG * ABYTES;
    uint32_t* msk = sm + NSTG * (BM * BK + BN * BK);   // 128 words

    const int tid  = threadIdx.x;
    const int lane = tid & 31;
    const int warp = tid >> 5;
    const int wm   = warp >> 2;          // 0..1 (M, 64 rows)
    const int wn   = warp & 3;           // 0..3 (N, 64 cols)

    const int bm = blockIdx.y * BM;
    const int bn = blockIdx.x * BN;

    // CTA mask slice: n-blocks [bn/16, bn/16+16), all 256 k-bits
    if (tid < 128) msk[tid] = g_maskW[(bn >> 4) * 8 + tid];
    __syncthreads();

    // ---- producer mapping: 8 threads per 128B row
    const int arow = tid >> 3;           // 0..31
    const int kq   = tid & 7;            // 16B quad within row
    const float* Ag = g_Xc + (size_t)(bm + arow) * K + kq * 4;
    const float* Wg = g_Wc + (size_t)(bn + arow) * K + kq * 4;
    const int swb = ((kq * 4) ^ ((arow & 7) * 4)) * 4;
    uint32_t sA[4], sB[8];
    int nbj[8];
    #pragma unroll
    for (int i = 0; i < 4; ++i) sA[i] = (uint32_t)((arow + i * 32) * 128 + swb);
    #pragma unroll
    for (int j = 0; j < 8; ++j) {
        sB[j]  = (uint32_t)((arow + j * 32) * 128 + swb);
        nbj[j] = (arow + j * 32) >> 4;   // local n-block of this B row
    }
    const int kqp = kq >> 2;             // k-block parity within stage

    // ---- ldmatrix addressing (hoisted)
    const int g = lane >> 3, r = lane & 7;
    const int ga = g >> 1, gb = g & 1;
    uint32_t aoff[4], boff[4];
    #pragma unroll
    for (int mt = 0; mt < 4; ++mt)
        aoff[mt] = (uint32_t)((wm * 64 + mt * 16 + (g & 1) * 8 + r) * 128);
    #pragma unroll
    for (int ntp = 0; ntp < 4; ++ntp)
        boff[ntp] = (uint32_t)((wn * 64 + (2 * ntp + (g >> 1)) * 8 + r) * 128);
    uint32_t qxa[4], qxb[4];
    #pragma unroll
    for (int kk = 0; kk < 4; ++kk) {
        qxa[kk] = (uint32_t)(((2 * kk + ga) ^ r) * 16);
        qxb[kk] = (uint32_t)(((2 * kk + gb) ^ r) * 16);
    }

    float acc[4][8][4];
    #pragma unroll
    for (int mt = 0; mt < 4; ++mt)
        #pragma unroll
        for (int nt = 0; nt < 8; ++nt)
            #pragma unroll
            for (int j = 0; j < 4; ++j) acc[mt][nt][j] = 0.0f;

    const int nk = K / BK;               // 128

    // stage issue: A always; B gated by block mask (skipped region never consumed)
    auto issue = [&](int t, int s) {
        const uint32_t Ab = sbase + (uint32_t)s * ABYTES;
        const uint32_t Bb = sbase + OFFB + (uint32_t)s * BBYTES;
        const float* Ap = Ag + (size_t)t * BK;
        const float* Wp = Wg + (size_t)t * BK;
        #pragma unroll
        for (int i = 0; i < 4; ++i) cpasync16(Ab + sA[i], Ap + (size_t)(i * 32) * K);
        const int kb = t * 2 + kqp;
        const int kw = kb >> 5;
        const uint32_t kbit = 1u << (kb & 31);
        #pragma unroll
        for (int j = 0; j < 8; ++j)
            if (msk[nbj[j] * 8 + kw] & kbit)
                cpasync16(Bb + sB[j], Wp + (size_t)(j * 32) * K);
    };

    // prologue: stages 0..2
    #pragma unroll
    for (int s = 0; s < NSTG - 1; ++s) { issue(s, s); cpcommit(); }

    for (int t = 0; t < nk; ++t) {
        cpwait<NSTG - 2>();
        __syncthreads();

        if (t + NSTG - 1 < nk) issue(t + NSTG - 1, (t + NSTG - 1) & (NSTG - 1));
        cpcommit();

        const uint32_t Ab = sbase + (uint32_t)(t & (NSTG - 1)) * ABYTES;
        const uint32_t Bb = sbase + OFFB + (uint32_t)(t & (NSTG - 1)) * BBYTES;

        // per-warp mask bits: 2 k-blocks x 4 n-blocks for this stage
        const int tw = t >> 4, sh = (t * 2) & 31;
        uint32_t mb[4];
        #pragma unroll
        for (int ntp = 0; ntp < 4; ++ntp)
            mb[ntp] = (msk[(wn * 4 + ntp) * 8 + tw] >> sh) & 3u;

        #pragma unroll
        for (int kk = 0; kk < 4; ++kk) {
            uint32_t a[4][4];
            #pragma unroll
            for (int mt = 0; mt < 4; ++mt)
                ldsm4(a[mt][0], a[mt][1], a[mt][2], a[mt][3], Ab + aoff[mt] + qxa[kk]);
            const uint32_t kkbit = 1u << (kk >> 1);
            #pragma unroll
            for (int ntp = 0; ntp < 4; ++ntp) {
                if (mb[ntp] & kkbit) {   // warp-uniform
                    uint32_t b0, b1, b2, b3;
                    ldsm4(b0, b1, b2, b3, Bb + boff[ntp] + qxb[kk]);
                    #pragma unroll
                    for (int mt = 0; mt < 4; ++mt) {
                        mma_tf32(acc[mt][2 * ntp],
                                 a[mt][0], a[mt][1], a[mt][2], a[mt][3], b0, b1);
                        mma_tf32(acc[mt][2 * ntp + 1],
                                 a[mt][0], a[mt][1], a[mt][2], a[mt][3], b2, b3);
                    }
                }
            }
        }
    }

    // ---- epilogue: bias + fp32 store
    const int row = lane >> 2;
    const int col = lane & 3;
    #pragma unroll
    for (int nt = 0; nt < 8; ++nt) {
        const int gn = bn + wn * 64 + nt * 8 + col * 2;
        const float2 bb = *(const float2*)(Bias + gn);
        #pragma unroll
        for (int mt = 0; mt < 4; ++mt) {
            const int gm = bm + wm * 64 + mt * 16 + row;
            float2 v0, v1;
            v0.x = acc[mt][nt][0] + bb.x; v0.y = acc[mt][nt][1] + bb.y;
            v1.x = acc[mt][nt][2] + bb.x; v1.y = acc[mt][nt][3] + bb.y;
            *(float2*)(Y + (size_t)gm * N + gn)       = v0;
            *(float2*)(Y + (size_t)(gm + 8) * N + gn) = v1;
        }
    }
}

extern "C" void kernel_launch(void* const* d_in, const int* in_sizes, int n_in,
                              void* d_out, int out_size) {
    const float* X    = (const float*)d_in[0];   // [M, 4096]
    const float* W    = (const float*)d_in[1];   // [4096, 4096]
    const float* Bias = (const float*)d_in[2];   // [4096]
    float* Y = (float*)d_out;

    const int K = 4096;
    const int M = in_sizes[0] / K;               // 8192

    float *Xc, *Wc;
    cudaGetSymbolAddress((void**)&Xc, g_Xc);
    cudaGetSymbolAddress((void**)&Wc, g_Wc);

    const int n4x = (M * K) / 4, n4w = (4096 * K) / 4;
    cvt_tf32<<<4096, 256>>>((const float4*)X, (float4*)Xc, n4x);
    cvt_tf32<<<4096, 256>>>((const float4*)W, (float4*)Wc, n4w);
    mask_kernel<<<8192, 256>>>(W);               // 65536 blocks, 1 warp each

    const size_t smem_bytes = (size_t)NSTG * (BM * BK + BN * BK) * 4 + 512; // 197120
    cudaFuncSetAttribute(bsl_sp, cudaFuncAttributeMaxDynamicSharedMemorySize,
                         (int)smem_bytes);

    dim3 grid(4096 / BN, M / BM);   // (16, 64), N fast for L2 reuse
    bsl_sp<<<grid, NT, smem_bytes>>>(Bias, Y);
}